// round 2
// baseline (speedup 1.0000x reference)
#include <cuda_runtime.h>
#include <math.h>

#define HCH 511
#define LSEQ 2048
#define NM 32
#define CHK 128
#define NCHK 16
#define KPAD 512
#define MPAD 1024
#define TWOH 1022

// ---------------- scratch (device globals; no allocation allowed) ----------------
__device__ float2 g_w [HCH * NM];
__device__ float2 g_c2[HCH * NM];
__device__ float2 g_wC[HCH * NM];
__device__ float  g_Wt[KPAD * MPAD];     // W transposed, zero padded: [k][m]
__device__ float  g_Yb[KPAD * LSEQ];     // gelu output, row 511 zeroed
__device__ float  g_Y2[TWOH * LSEQ];     // GEMM output
__device__ float  g_Za[HCH * LSEQ];      // ping-pong activations
__device__ float  g_Zb[HCH * LSEQ];

__device__ __forceinline__ const float* zsrc_ptr(int sel, const float* ext) {
    return sel < 0 ? ext : (sel == 0 ? g_Za : g_Zb);
}

// ---------------- f32x2 packed-FMA helpers ----------------
__device__ __forceinline__ unsigned long long fma2(unsigned long long a,
                                                   unsigned long long b,
                                                   unsigned long long c) {
    unsigned long long d;
    asm("fma.rn.f32x2 %0, %1, %2, %3;" : "=l"(d) : "l"(a), "l"(b), "l"(c));
    return d;
}
__device__ __forceinline__ unsigned long long pack2(float x, float y) {
    unsigned long long d;
    asm("mov.b64 %0, {%1, %2};" : "=l"(d) : "f"(x), "f"(y));
    return d;
}
union F4U { float4 f; unsigned long long u[2]; };

// ---------------- prep: per-mode discretized SSM constants ----------------
__global__ void kprep_kernel(const float* __restrict__ log_dt, const float* __restrict__ Arl,
                             const float* __restrict__ Aim, const float* __restrict__ Cre,
                             const float* __restrict__ Cim) {
    int idx = blockIdx.x * blockDim.x + threadIdx.x;
    if (idx >= HCH * NM) return;
    int h = idx >> 5;
    float dt  = expf(log_dt[h]);
    float Ar  = -expf(Arl[idx]);
    float Ai  = Aim[idx];
    float dar = Ar * dt, dai = Ai * dt;
    float er  = expf(dar);
    float wr  = er * cosf(dai);
    float wi  = er * sinf(dai);
    // Ccoef = (Cre + i Cim) * (w - 1) / A ; store 2*Ccoef
    float e1r = wr - 1.f, e1i = wi;
    float inv = 1.f / (Ar * Ar + Ai * Ai);
    float fr  = (e1r * Ar + e1i * Ai) * inv;
    float fi  = (e1i * Ar - e1r * Ai) * inv;
    float cr  = Cre[idx] * fr - Cim[idx] * fi;
    float ci  = Cre[idx] * fi + Cim[idx] * fr;
    g_w[idx]  = make_float2(wr, wi);
    g_c2[idx] = make_float2(2.f * cr, 2.f * ci);
    // w^CHK in double for an accurate chunk-jump multiplier
    double ph = (double)dai * (double)CHK;
    double sv, cv;
    sincos(ph, &sv, &cv);
    double eC = exp((double)dar * (double)CHK);
    g_wC[idx] = make_float2((float)(eC * cv), (float)(eC * sv));
}

// ---------------- prep: transpose + zero-pad glu_w; zero Yb pad row ----------------
__global__ void wprep_kernel(const float* __restrict__ gw) {
    int idx = blockIdx.x * blockDim.x + threadIdx.x;   // 0 .. 512*1024-1
    int k = idx >> 10;
    int m = idx & 1023;
    g_Wt[idx] = (k < HCH && m < TWOH) ? gw[m * HCH + k] : 0.f;
    if (idx < LSEQ) g_Yb[HCH * LSEQ + idx] = 0.f;
}

// ---------------- conv: chunked parallel scan over L, per channel ----------------
__global__ __launch_bounds__(512) void conv_kernel(const float* __restrict__ Zext,
                                                   const float* __restrict__ Dsk, int src) {
    __shared__ float  zs[LSEQ];
    __shared__ float  ys[LSEQ];
    __shared__ float2 st[NCHK][NM];
    __shared__ float2 sinit[NCHK][NM];
    int h    = blockIdx.x;
    int tid  = threadIdx.x;
    int wid  = tid >> 5;
    int lane = tid & 31;
    const float* zrow = zsrc_ptr(src, Zext) + h * LSEQ;
    for (int i = tid; i < LSEQ; i += 512) zs[i] = zrow[i];
    float2 w = g_w[h * NM + lane];
    float2 c = g_c2[h * NM + lane];
    __syncthreads();

    // Pass A: per-chunk local final state (zero init)
    {
        float sr = 0.f, si = 0.f;
        int base = wid * CHK;
        #pragma unroll 8
        for (int j = 0; j < CHK; j++) {
            float zv = zs[base + j];
            float nr = fmaf(w.x, sr, fmaf(-w.y, si, zv));
            float ni = fmaf(w.y, sr, w.x * si);
            sr = nr; si = ni;
        }
        st[wid][lane] = make_float2(sr, si);
    }
    __syncthreads();

    // cross-chunk scan (warp 0, lane = mode)
    if (wid == 0) {
        float2 wc = g_wC[h * NM + lane];
        float cr = 0.f, ci = 0.f;
        #pragma unroll
        for (int jc = 0; jc < NCHK; jc++) {
            sinit[jc][lane] = make_float2(cr, ci);
            float2 b = st[jc][lane];
            float nr = fmaf(wc.x, cr, fmaf(-wc.y, ci, b.x));
            float ni = fmaf(wc.y, cr, fmaf(wc.x, ci, b.y));
            cr = nr; ci = ni;
        }
    }
    __syncthreads();

    // Pass C: re-scan with true init state, emit y[l] = 2 Re(sum_n c_n s_n)
    {
        float2 s0 = sinit[wid][lane];
        float sr = s0.x, si = s0.y;
        int base = wid * CHK;
        #pragma unroll 4
        for (int j = 0; j < CHK; j++) {
            float zv = zs[base + j];
            float nr = fmaf(w.x, sr, fmaf(-w.y, si, zv));
            float ni = fmaf(w.y, sr, w.x * si);
            sr = nr; si = ni;
            float v = fmaf(c.x, nr, -c.y * ni);
            v += __shfl_xor_sync(0xffffffffu, v, 16);
            v += __shfl_xor_sync(0xffffffffu, v, 8);
            v += __shfl_xor_sync(0xffffffffu, v, 4);
            v += __shfl_xor_sync(0xffffffffu, v, 2);
            v += __shfl_xor_sync(0xffffffffu, v, 1);
            if (lane == 0) ys[base + j] = v;
        }
    }
    float Dh = Dsk[h];
    __syncthreads();

    // epilogue: + D*z, gelu(tanh approx), coalesced write
    float* yrow = g_Yb + h * LSEQ;
    for (int i = tid; i < LSEQ; i += 512) {
        float x  = fmaf(Dh, zs[i], ys[i]);
        float x3 = x * x * x;
        float t  = tanhf(0.7978845608028654f * fmaf(0.044715f, x3, x));
        yrow[i]  = 0.5f * x * (1.f + t);
    }
}

// ---------------- GEMM: Y2[1022,2048] = Wt^T @ Yb  (fp32, packed f32x2 FMA) -------
__global__ __launch_bounds__(256) void gemm_kernel() {
    __shared__ float As[2][16][128];
    __shared__ float Bs[2][16][128];
    const int t  = threadIdx.x;
    const int n0 = blockIdx.x * 128;
    const int m0 = blockIdx.y * 128;
    const int tx = t & 15;        // n-octet
    const int ty = t >> 4;        // m-octet
    const int k1  = t >> 5;       // 0..7
    const int k2  = k1 + 8;
    const int col = (t & 31) * 4;

    unsigned long long acc[8][4];
    #pragma unroll
    for (int i = 0; i < 8; i++)
        #pragma unroll
        for (int j = 0; j < 4; j++) acc[i][j] = 0ull;

    // prologue: stage kt=0
    {
        float4 a0 = *(const float4*)&g_Wt[(0 + k1) * MPAD + m0 + col];
        float4 a1 = *(const float4*)&g_Wt[(0 + k2) * MPAD + m0 + col];
        float4 b0 = *(const float4*)&g_Yb[(0 + k1) * LSEQ + n0 + col];
        float4 b1 = *(const float4*)&g_Yb[(0 + k2) * LSEQ + n0 + col];
        *(float4*)&As[0][k1][col] = a0;
        *(float4*)&As[0][k2][col] = a1;
        *(float4*)&Bs[0][k1][col] = b0;
        *(float4*)&Bs[0][k2][col] = b1;
    }
    __syncthreads();

    int buf = 0;
    for (int kt = 0; kt < KPAD; kt += 16) {
        float4 pa0, pa1, pb0, pb1;
        const bool has = (kt + 16) < KPAD;
        if (has) {
            pa0 = *(const float4*)&g_Wt[(kt + 16 + k1) * MPAD + m0 + col];
            pa1 = *(const float4*)&g_Wt[(kt + 16 + k2) * MPAD + m0 + col];
            pb0 = *(const float4*)&g_Yb[(kt + 16 + k1) * LSEQ + n0 + col];
            pb1 = *(const float4*)&g_Yb[(kt + 16 + k2) * LSEQ + n0 + col];
        }
        #pragma unroll
        for (int kk = 0; kk < 16; kk++) {
            F4U a0, a1, b0, b1;
            a0.f = *(const float4*)&As[buf][kk][ty * 8];
            a1.f = *(const float4*)&As[buf][kk][ty * 8 + 4];
            b0.f = *(const float4*)&Bs[buf][kk][tx * 8];
            b1.f = *(const float4*)&Bs[buf][kk][tx * 8 + 4];
            unsigned long long bb[4] = {b0.u[0], b0.u[1], b1.u[0], b1.u[1]};
            float av[8] = {a0.f.x, a0.f.y, a0.f.z, a0.f.w, a1.f.x, a1.f.y, a1.f.z, a1.f.w};
            #pragma unroll
            for (int i = 0; i < 8; i++) {
                unsigned long long ap = pack2(av[i], av[i]);
                #pragma unroll
                for (int j = 0; j < 4; j++) acc[i][j] = fma2(ap, bb[j], acc[i][j]);
            }
        }
        if (has) {
            *(float4*)&As[buf ^ 1][k1][col] = pa0;
            *(float4*)&As[buf ^ 1][k2][col] = pa1;
            *(float4*)&Bs[buf ^ 1][k1][col] = pb0;
            *(float4*)&Bs[buf ^ 1][k2][col] = pb1;
        }
        __syncthreads();
        buf ^= 1;
    }

    #pragma unroll
    for (int i = 0; i < 8; i++) {
        int m = m0 + ty * 8 + i;
        if (m < TWOH) {
            F4U o0, o1;
            o0.u[0] = acc[i][0]; o0.u[1] = acc[i][1];
            o1.u[0] = acc[i][2]; o1.u[1] = acc[i][3];
            *(float4*)&g_Y2[m * LSEQ + n0 + tx * 8]     = o0.f;
            *(float4*)&g_Y2[m * LSEQ + n0 + tx * 8 + 4] = o1.f;
        }
    }
}

// ---------------- GLU + bias + residual + channel LayerNorm ----------------
__global__ __launch_bounds__(512) void lnglu_kernel(const float* __restrict__ Zext,
                                                    const float* __restrict__ gb,
                                                    const float* __restrict__ lng,
                                                    const float* __restrict__ lnb,
                                                    float* __restrict__ ext_out,
                                                    int src, int dst) {
    const float* res = zsrc_ptr(src, Zext);
    float* outp = dst < 0 ? ext_out : (dst == 0 ? g_Za : g_Zb);
    int tx = threadIdx.x & 31;
    int ty = threadIdx.x >> 5;          // 0..15
    int l  = blockIdx.x * 32 + tx;

    float s1 = 0.f, s2 = 0.f;
    for (int h = ty; h < HCH; h += 16) {
        float a = g_Y2[h * LSEQ + l] + gb[h];
        float b = g_Y2[(h + HCH) * LSEQ + l] + gb[h + HCH];
        float g = a / (1.f + expf(-b)) + res[h * LSEQ + l];
        s1 += g; s2 += g * g;
    }
    __shared__ float r1[16][33], r2[16][33];
    __shared__ float mu_s[32], rs_s[32];
    r1[ty][tx] = s1; r2[ty][tx] = s2;
    __syncthreads();
    if (ty == 0) {
        float a1 = 0.f, a2 = 0.f;
        #pragma unroll
        for (int j = 0; j < 16; j++) { a1 += r1[j][tx]; a2 += r2[j][tx]; }
        float mu  = a1 * (1.f / (float)HCH);
        float var = a2 * (1.f / (float)HCH) - mu * mu;
        mu_s[tx] = mu;
        rs_s[tx] = rsqrtf(var + 1e-5f);
    }
    __syncthreads();
    float mu = mu_s[tx], rs = rs_s[tx];
    for (int h = ty; h < HCH; h += 16) {
        float a = g_Y2[h * LSEQ + l] + gb[h];
        float b = g_Y2[(h + HCH) * LSEQ + l] + gb[h + HCH];
        float g = a / (1.f + expf(-b)) + res[h * LSEQ + l];
        outp[h * LSEQ + l] = (g - mu) * rs * lng[h] + lnb[h];
    }
}

// ---------------- launch ----------------
extern "C" void kernel_launch(void* const* d_in, const int* in_sizes, int n_in,
                              void* d_out, int out_size) {
    const float* Z      = (const float*)d_in[0];
    const float* log_dt = (const float*)d_in[1];
    const float* Arl    = (const float*)d_in[2];
    const float* Aim    = (const float*)d_in[3];
    const float* Cre    = (const float*)d_in[4];
    const float* Cim    = (const float*)d_in[5];
    const float* Dsk    = (const float*)d_in[6];
    const float* gw     = (const float*)d_in[7];
    const float* gb     = (const float*)d_in[8];
    const float* lng    = (const float*)d_in[9];
    const float* lnb    = (const float*)d_in[10];
    float* out = (float*)d_out;

    kprep_kernel<<<(HCH * NM + 255) / 256, 256>>>(log_dt, Arl, Aim, Cre, Cim);
    wprep_kernel<<<(KPAD * MPAD) / 256, 256>>>(gw);

    // layer i: src activation sel, dst activation sel (-1 = external)
    const int srcs[4] = {-1, 0, 1, 0};
    const int dsts[4] = { 0, 1, 0, -1};
    for (int layer = 0; layer < 4; ++layer) {
        conv_kernel<<<HCH, 512>>>(Z, Dsk, srcs[layer]);
        gemm_kernel<<<dim3(16, 8), 256>>>();
        lnglu_kernel<<<LSEQ / 32, 512>>>(Z, gb, lng, lnb, out, srcs[layer], dsts[layer]);
    }
}

// round 4
// speedup vs baseline: 1.1521x; 1.1521x over previous
#include <cuda_runtime.h>
#include <cuda_bf16.h>
#include <math.h>
#include <stdint.h>

#define HCH 511
#define LSEQ 2048
#define NM 32
#define CHK 128
#define NCHK 16
#define KPAD 512
#define MPAD 1024
#define TWOH 1022

// ---------------- scratch (device globals; no allocation allowed) ----------------
__device__ float2 g_w [HCH * NM];
__device__ float2 g_c2[HCH * NM];
__device__ float2 g_wC[HCH * NM];
__device__ float  g_Yb[KPAD * LSEQ];            // gelu output fp32, row 511 zeroed
__device__ float  g_Y2[TWOH * LSEQ];            // GEMM output
__device__ float  g_Za[HCH * LSEQ];             // ping-pong activations
__device__ float  g_Zb[HCH * LSEQ];
__device__ __nv_bfloat16 g_Ahi[MPAD * KPAD];    // weight split, K-major, zero padded
__device__ __nv_bfloat16 g_Alo[MPAD * KPAD];
__device__ __nv_bfloat16 g_Bhi[LSEQ * KPAD];    // activation split, [n][k]
__device__ __nv_bfloat16 g_Blo[LSEQ * KPAD];

__device__ __forceinline__ const float* zsrc_ptr(int sel, const float* ext) {
    return sel < 0 ? ext : (sel == 0 ? g_Za : g_Zb);
}

// ---------------- prep: per-mode discretized SSM constants ----------------
__global__ void kprep_kernel(const float* __restrict__ log_dt, const float* __restrict__ Arl,
                             const float* __restrict__ Aim, const float* __restrict__ Cre,
                             const float* __restrict__ Cim) {
    int idx = blockIdx.x * blockDim.x + threadIdx.x;
    if (idx >= HCH * NM) return;
    int h = idx >> 5;
    float dt  = expf(log_dt[h]);
    float Ar  = -expf(Arl[idx]);
    float Ai  = Aim[idx];
    float dar = Ar * dt, dai = Ai * dt;
    float er  = expf(dar);
    float wr  = er * cosf(dai);
    float wi  = er * sinf(dai);
    float e1r = wr - 1.f, e1i = wi;
    float inv = 1.f / (Ar * Ar + Ai * Ai);
    float fr  = (e1r * Ar + e1i * Ai) * inv;
    float fi  = (e1i * Ar - e1r * Ai) * inv;
    float cr  = Cre[idx] * fr - Cim[idx] * fi;
    float ci  = Cre[idx] * fi + Cim[idx] * fr;
    g_w[idx]  = make_float2(wr, wi);
    g_c2[idx] = make_float2(2.f * cr, 2.f * ci);
    double ph = (double)dai * (double)CHK;
    double sv, cv;
    sincos(ph, &sv, &cv);
    double eC = exp((double)dar * (double)CHK);
    g_wC[idx] = make_float2((float)(eC * cv), (float)(eC * sv));
}

// ---------------- prep: split glu_w into bf16 hi/lo, K-major, zero padded --------
__global__ void asplit_kernel(const float* __restrict__ gw) {
    int idx = blockIdx.x * blockDim.x + threadIdx.x;   // 0 .. 1024*512-1
    int m = idx >> 9;
    int k = idx & 511;
    float v = (m < TWOH && k < HCH) ? gw[m * HCH + k] : 0.f;
    __nv_bfloat16 hi = __float2bfloat16(v);
    g_Ahi[idx] = hi;
    g_Alo[idx] = __float2bfloat16(v - __bfloat162float(hi));
    if (idx < LSEQ) g_Yb[HCH * LSEQ + idx] = 0.f;   // zero pad row of Yb
}

// ---------------- conv: chunked parallel scan over L, per channel ----------------
__global__ __launch_bounds__(512) void conv_kernel(const float* __restrict__ Zext,
                                                   const float* __restrict__ Dsk, int src) {
    __shared__ float  zs[LSEQ];
    __shared__ float  ys[LSEQ];
    __shared__ float2 st[NCHK][NM];
    __shared__ float2 sinit[NCHK][NM];
    int h    = blockIdx.x;
    int tid  = threadIdx.x;
    int wid  = tid >> 5;
    int lane = tid & 31;
    const float* zrow = zsrc_ptr(src, Zext) + h * LSEQ;
    for (int i = tid; i < LSEQ; i += 512) zs[i] = zrow[i];
    float2 w = g_w[h * NM + lane];
    float2 c = g_c2[h * NM + lane];
    __syncthreads();

    {   // Pass A: per-chunk local final state (zero init)
        float sr = 0.f, si = 0.f;
        int base = wid * CHK;
        #pragma unroll 8
        for (int j = 0; j < CHK; j++) {
            float zv = zs[base + j];
            float nr = fmaf(w.x, sr, fmaf(-w.y, si, zv));
            float ni = fmaf(w.y, sr, w.x * si);
            sr = nr; si = ni;
        }
        st[wid][lane] = make_float2(sr, si);
    }
    __syncthreads();

    if (wid == 0) {   // cross-chunk scan
        float2 wc = g_wC[h * NM + lane];
        float cr = 0.f, ci = 0.f;
        #pragma unroll
        for (int jc = 0; jc < NCHK; jc++) {
            sinit[jc][lane] = make_float2(cr, ci);
            float2 b = st[jc][lane];
            float nr = fmaf(wc.x, cr, fmaf(-wc.y, ci, b.x));
            float ni = fmaf(wc.y, cr, fmaf(wc.x, ci, b.y));
            cr = nr; ci = ni;
        }
    }
    __syncthreads();

    {   // Pass C: re-scan with true init, emit y
        float2 s0 = sinit[wid][lane];
        float sr = s0.x, si = s0.y;
        int base = wid * CHK;
        #pragma unroll 4
        for (int j = 0; j < CHK; j++) {
            float zv = zs[base + j];
            float nr = fmaf(w.x, sr, fmaf(-w.y, si, zv));
            float ni = fmaf(w.y, sr, w.x * si);
            sr = nr; si = ni;
            float v = fmaf(c.x, nr, -c.y * ni);
            v += __shfl_xor_sync(0xffffffffu, v, 16);
            v += __shfl_xor_sync(0xffffffffu, v, 8);
            v += __shfl_xor_sync(0xffffffffu, v, 4);
            v += __shfl_xor_sync(0xffffffffu, v, 2);
            v += __shfl_xor_sync(0xffffffffu, v, 1);
            if (lane == 0) ys[base + j] = v;
        }
    }
    float Dh = Dsk[h];
    __syncthreads();

    float* yrow = g_Yb + h * LSEQ;
    for (int i = tid; i < LSEQ; i += 512) {
        float x  = fmaf(Dh, zs[i], ys[i]);
        float x3 = x * x * x;
        float t  = tanhf(0.7978845608028654f * fmaf(0.044715f, x3, x));
        yrow[i]  = 0.5f * x * (1.f + t);
    }
}

// ---------------- transpose + bf16 split: Yb[512][2048] -> Bhi/Blo[2048][512] -----
__global__ __launch_bounds__(256) void tsplit_kernel() {
    __shared__ float ts[32][33];
    int kx = blockIdx.x * 32;
    int nx = blockIdx.y * 32;
    int c = threadIdx.x & 31;
    int r = threadIdx.x >> 5;   // 0..7
    #pragma unroll
    for (int rr = 0; rr < 4; rr++)
        ts[r + rr * 8][c] = g_Yb[(kx + r + rr * 8) * LSEQ + nx + c];
    __syncthreads();
    #pragma unroll
    for (int rr = 0; rr < 4; rr++) {
        int n = nx + r + rr * 8;
        float v = ts[c][r + rr * 8];
        __nv_bfloat16 hi = __float2bfloat16(v);
        g_Bhi[n * KPAD + kx + c] = hi;
        g_Blo[n * KPAD + kx + c] = __float2bfloat16(v - __bfloat162float(hi));
    }
}

// ---------------- HMMA GEMM: Y2[1022,2048] = A @ B^T (split-bf16, mma.sync) -------
// K' = 3*512: segments (Ahi,Bhi), (Ahi,Blo), (Alo,Bhi)

__device__ __forceinline__ void cp16(uint32_t saddr, const void* gptr) {
    asm volatile("cp.async.ca.shared.global [%0], [%1], 16;" :: "r"(saddr), "l"(gptr));
}
__device__ __forceinline__ uint32_t swz(int row, int ch) {
    return (uint32_t)(row * 64 + ((ch ^ ((row >> 1) & 3)) << 4));
}

__global__ __launch_bounds__(256, 1) void gemm_hmma_kernel() {
    __shared__ __align__(128) char sA[2][8192];
    __shared__ __align__(128) char sB[2][8192];

    const int t    = threadIdx.x;
    const int wid  = t >> 5;
    const int lane = t & 31;
    const int n0   = blockIdx.x * 128;
    const int m0   = blockIdx.y * 128;
    const int wm   = (wid & 1) * 64;      // warp m offset
    const int wn   = (wid >> 1) * 32;     // warp n offset

    const uint32_t sAu = (uint32_t)__cvta_generic_to_shared(&sA[0][0]);
    const uint32_t sBu = (uint32_t)__cvta_generic_to_shared(&sB[0][0]);

    // per-thread load slots: 2 rows each for A and B
    const int lrow0 = t >> 2, lch = t & 3;
    const int lrow1 = lrow0 + 64;
    const uint32_t so0 = swz(lrow0, lch);
    const uint32_t so1 = swz(lrow1, lch);

    // ldmatrix lane geometry
    const int ra  = lane & 15;            // A row within 16
    const int ca  = lane >> 4;            // A k-half (0/1)
    const int rb  = ((lane >> 4) << 3) + (lane & 7);  // B row within 16
    const int cb  = (lane >> 3) & 1;      // B k-half

    const __nv_bfloat16* Asegs[3] = {g_Ahi, g_Ahi, g_Alo};
    const __nv_bfloat16* Bsegs[3] = {g_Bhi, g_Blo, g_Bhi};

    float acc[4][4][4];
    #pragma unroll
    for (int i = 0; i < 4; i++)
        #pragma unroll
        for (int j = 0; j < 4; j++)
            #pragma unroll
            for (int q = 0; q < 4; q++) acc[i][j][q] = 0.f;

    // prologue: chunk 0
    {
        const __nv_bfloat16* Ap = Asegs[0];
        const __nv_bfloat16* Bp = Bsegs[0];
        cp16(sAu + so0, Ap + (m0 + lrow0) * KPAD + lch * 8);
        cp16(sAu + so1, Ap + (m0 + lrow1) * KPAD + lch * 8);
        cp16(sBu + so0, Bp + (n0 + lrow0) * KPAD + lch * 8);
        cp16(sBu + so1, Bp + (n0 + lrow1) * KPAD + lch * 8);
        asm volatile("cp.async.commit_group;" ::: "memory");
    }

    for (int it = 0; it < 48; it++) {
        const int buf = it & 1;
        const uint32_t sAb = sAu + buf * 8192;
        const uint32_t sBb = sBu + buf * 8192;

        if (it + 1 < 48) {
            const int nit = it + 1;
            const int seg = nit >> 4, kc = nit & 15;
            const __nv_bfloat16* Ap = Asegs[seg];
            const __nv_bfloat16* Bp = Bsegs[seg];
            const uint32_t dA = sAu + (nit & 1) * 8192;
            const uint32_t dB = sBu + (nit & 1) * 8192;
            const int kb = kc * 32 + lch * 8;
            cp16(dA + so0, Ap + (m0 + lrow0) * KPAD + kb);
            cp16(dA + so1, Ap + (m0 + lrow1) * KPAD + kb);
            cp16(dB + so0, Bp + (n0 + lrow0) * KPAD + kb);
            cp16(dB + so1, Bp + (n0 + lrow1) * KPAD + kb);
            asm volatile("cp.async.commit_group;" ::: "memory");
            asm volatile("cp.async.wait_group 1;" ::: "memory");
        } else {
            asm volatile("cp.async.wait_group 0;" ::: "memory");
        }
        __syncthreads();

        #pragma unroll
        for (int ks = 0; ks < 2; ks++) {
            const int kc2 = ks * 2;
            uint32_t a[4][4], b[4][2];
            #pragma unroll
            for (int mt = 0; mt < 4; mt++) {
                int row = wm + mt * 16 + ra;
                uint32_t ad = sAb + swz(row, kc2 + ca);
                asm volatile("ldmatrix.sync.aligned.m8n8.x4.shared.b16 {%0,%1,%2,%3}, [%4];"
                             : "=r"(a[mt][0]), "=r"(a[mt][1]), "=r"(a[mt][2]), "=r"(a[mt][3])
                             : "r"(ad));
            }
            #pragma unroll
            for (int np = 0; np < 2; np++) {
                int row = wn + np * 16 + rb;
                uint32_t bd = sBb + swz(row, kc2 + cb);
                uint32_t r0, r1, r2, r3;
                asm volatile("ldmatrix.sync.aligned.m8n8.x4.shared.b16 {%0,%1,%2,%3}, [%4];"
                             : "=r"(r0), "=r"(r1), "=r"(r2), "=r"(r3) : "r"(bd));
                b[np * 2][0] = r0; b[np * 2][1] = r1;
                b[np * 2 + 1][0] = r2; b[np * 2 + 1][1] = r3;
            }
            #pragma unroll
            for (int mt = 0; mt < 4; mt++)
                #pragma unroll
                for (int nt = 0; nt < 4; nt++) {
                    asm volatile(
                        "mma.sync.aligned.m16n8k16.row.col.f32.bf16.bf16.f32 "
                        "{%0,%1,%2,%3}, {%4,%5,%6,%7}, {%8,%9}, {%0,%1,%2,%3};"
                        : "+f"(acc[mt][nt][0]), "+f"(acc[mt][nt][1]),
                          "+f"(acc[mt][nt][2]), "+f"(acc[mt][nt][3])
                        : "r"(a[mt][0]), "r"(a[mt][1]), "r"(a[mt][2]), "r"(a[mt][3]),
                          "r"(b[nt][0]), "r"(b[nt][1]));
                }
        }
        __syncthreads();
    }

    // epilogue
    #pragma unroll
    for (int mt = 0; mt < 4; mt++) {
        int mr0 = m0 + wm + mt * 16 + (lane >> 2);
        #pragma unroll
        for (int nt = 0; nt < 4; nt++) {
            int nc = n0 + wn + nt * 8 + (lane & 3) * 2;
            if (mr0 < TWOH)
                *reinterpret_cast<float2*>(&g_Y2[mr0 * LSEQ + nc]) =
                    make_float2(acc[mt][nt][0], acc[mt][nt][1]);
            if (mr0 + 8 < TWOH)
                *reinterpret_cast<float2*>(&g_Y2[(mr0 + 8) * LSEQ + nc]) =
                    make_float2(acc[mt][nt][2], acc[mt][nt][3]);
        }
    }
}

// ---------------- GLU + bias + residual + channel LayerNorm ----------------
__global__ __launch_bounds__(512) void lnglu_kernel(const float* __restrict__ Zext,
                                                    const float* __restrict__ gb,
                                                    const float* __restrict__ lng,
                                                    const float* __restrict__ lnb,
                                                    float* __restrict__ ext_out,
                                                    int src, int dst) {
    const float* res = zsrc_ptr(src, Zext);
    float* outp = dst < 0 ? ext_out : (dst == 0 ? g_Za : g_Zb);
    int tx = threadIdx.x & 31;
    int ty = threadIdx.x >> 5;          // 0..15
    int l  = blockIdx.x * 32 + tx;

    float s1 = 0.f, s2 = 0.f;
    for (int h = ty; h < HCH; h += 16) {
        float a = g_Y2[h * LSEQ + l] + gb[h];
        float b = g_Y2[(h + HCH) * LSEQ + l] + gb[h + HCH];
        float g = a / (1.f + expf(-b)) + res[h * LSEQ + l];
        s1 += g; s2 += g * g;
    }
    __shared__ float r1[16][33], r2[16][33];
    __shared__ float mu_s[32], rs_s[32];
    r1[ty][tx] = s1; r2[ty][tx] = s2;
    __syncthreads();
    if (ty == 0) {
        float a1 = 0.f, a2 = 0.f;
        #pragma unroll
        for (int j = 0; j < 16; j++) { a1 += r1[j][tx]; a2 += r2[j][tx]; }
        float mu  = a1 * (1.f / (float)HCH);
        float var = a2 * (1.f / (float)HCH) - mu * mu;
        mu_s[tx] = mu;
        rs_s[tx] = rsqrtf(var + 1e-5f);
    }
    __syncthreads();
    float mu = mu_s[tx], rs = rs_s[tx];
    for (int h = ty; h < HCH; h += 16) {
        float a = g_Y2[h * LSEQ + l] + gb[h];
        float b = g_Y2[(h + HCH) * LSEQ + l] + gb[h + HCH];
        float g = a / (1.f + expf(-b)) + res[h * LSEQ + l];
        outp[h * LSEQ + l] = (g - mu) * rs * lng[h] + lnb[h];
    }
}

// ---------------- launch ----------------
extern "C" void kernel_launch(void* const* d_in, const int* in_sizes, int n_in,
                              void* d_out, int out_size) {
    const float* Z      = (const float*)d_in[0];
    const float* log_dt = (const float*)d_in[1];
    const float* Arl    = (const float*)d_in[2];
    const float* Aim    = (const float*)d_in[3];
    const float* Cre    = (const float*)d_in[4];
    const float* Cim    = (const float*)d_in[5];
    const float* Dsk    = (const float*)d_in[6];
    const float* gw     = (const float*)d_in[7];
    const float* gb     = (const float*)d_in[8];
    const float* lng    = (const float*)d_in[9];
    const float* lnb    = (const float*)d_in[10];
    float* out = (float*)d_out;

    kprep_kernel<<<(HCH * NM + 255) / 256, 256>>>(log_dt, Arl, Aim, Cre, Cim);
    asplit_kernel<<<(MPAD * KPAD) / 256, 256>>>(gw);

    const int srcs[4] = {-1, 0, 1, 0};
    const int dsts[4] = { 0, 1, 0, -1};
    for (int layer = 0; layer < 4; ++layer) {
        conv_kernel<<<HCH, 512>>>(Z, Dsk, srcs[layer]);
        tsplit_kernel<<<dim3(KPAD / 32, LSEQ / 32), 256>>>();
        gemm_hmma_kernel<<<dim3(16, 8), 256>>>();
        lnglu_kernel<<<LSEQ / 32, 512>>>(Z, gb, lng, lnb, out, srcs[layer], dsts[layer]);
    }
}

// round 5
// speedup vs baseline: 1.3352x; 1.1589x over previous
#include <cuda_runtime.h>
#include <cuda_bf16.h>
#include <math.h>
#include <stdint.h>

#define HCH 511
#define LSEQ 2048
#define NM 32
#define CHK 128
#define NCHK 16
#define KPAD 512
#define MPAD 1024
#define TWOH 1022

// ---------------- scratch (device globals) ----------------
__device__ float2 g_w [HCH * NM];
__device__ float2 g_c2[HCH * NM];
__device__ float2 g_wC[HCH * NM];
__device__ float  g_Y2[TWOH * LSEQ];            // GEMM output
__device__ float  g_Za[HCH * LSEQ];             // ping-pong activations
__device__ float  g_Zb[HCH * LSEQ];
__device__ __nv_bfloat16 g_Ahi[MPAD * KPAD];    // weight split, [m][k], zero padded
__device__ __nv_bfloat16 g_Alo[MPAD * KPAD];
__device__ __nv_bfloat16 g_Bhi[KPAD * LSEQ];    // activation split, K-major [k][n]
__device__ __nv_bfloat16 g_Blo[KPAD * LSEQ];

__device__ __forceinline__ const float* zsrc_ptr(int sel, const float* ext) {
    return sel < 0 ? ext : (sel == 0 ? g_Za : g_Zb);
}

// ---------------- prep: per-mode discretized SSM constants ----------------
__global__ void kprep_kernel(const float* __restrict__ log_dt, const float* __restrict__ Arl,
                             const float* __restrict__ Aim, const float* __restrict__ Cre,
                             const float* __restrict__ Cim) {
    int idx = blockIdx.x * blockDim.x + threadIdx.x;
    if (idx >= HCH * NM) return;
    int h = idx >> 5;
    float dt  = expf(log_dt[h]);
    float Ar  = -expf(Arl[idx]);
    float Ai  = Aim[idx];
    float dar = Ar * dt, dai = Ai * dt;
    float er  = expf(dar);
    float wr  = er * cosf(dai);
    float wi  = er * sinf(dai);
    float e1r = wr - 1.f, e1i = wi;
    float inv = 1.f / (Ar * Ar + Ai * Ai);
    float fr  = (e1r * Ar + e1i * Ai) * inv;
    float fi  = (e1i * Ar - e1r * Ai) * inv;
    float cr  = Cre[idx] * fr - Cim[idx] * fi;
    float ci  = Cre[idx] * fi + Cim[idx] * fr;
    g_w[idx]  = make_float2(wr, wi);
    g_c2[idx] = make_float2(2.f * cr, 2.f * ci);
    double ph = (double)dai * (double)CHK;
    double sv, cv;
    sincos(ph, &sv, &cv);
    double eC = exp((double)dar * (double)CHK);
    g_wC[idx] = make_float2((float)(eC * cv), (float)(eC * sv));
}

// ---------------- prep: split glu_w into bf16 hi/lo; zero pad rows --------------
__global__ void asplit_kernel(const float* __restrict__ gw) {
    int idx = blockIdx.x * blockDim.x + threadIdx.x;   // 0 .. 1024*512-1
    int m = idx >> 9;
    int k = idx & 511;
    float v = (m < TWOH && k < HCH) ? gw[m * HCH + k] : 0.f;
    __nv_bfloat16 hi = __float2bfloat16(v);
    g_Ahi[idx] = hi;
    g_Alo[idx] = __float2bfloat16(v - __bfloat162float(hi));
    if (idx < LSEQ) {   // zero the k=511 pad row of B
        g_Bhi[HCH * LSEQ + idx] = __float2bfloat16(0.f);
        g_Blo[HCH * LSEQ + idx] = __float2bfloat16(0.f);
    }
}

// ---------------- conv: chunked parallel scan; writes bf16-split B rows ----------
__global__ __launch_bounds__(512) void conv_kernel(const float* __restrict__ Zext,
                                                   const float* __restrict__ Dsk, int src) {
    __shared__ float  zs[LSEQ];
    __shared__ float  vbuf[NCHK][CHK][4];
    __shared__ float2 st[NCHK][NM];
    __shared__ float2 sinit[NCHK][NM];
    int h    = blockIdx.x;
    int tid  = threadIdx.x;
    int wid  = tid >> 5;
    int lane = tid & 31;
    const float* zrow = zsrc_ptr(src, Zext) + h * LSEQ;
    for (int i = tid; i < LSEQ; i += 512) zs[i] = zrow[i];
    float2 w = g_w[h * NM + lane];
    float2 c = g_c2[h * NM + lane];
    __syncthreads();

    {   // Pass A: per-chunk local final state (zero init)
        float sr = 0.f, si = 0.f;
        int base = wid * CHK;
        #pragma unroll 8
        for (int j = 0; j < CHK; j++) {
            float zv = zs[base + j];
            float nr = fmaf(w.x, sr, fmaf(-w.y, si, zv));
            float ni = fmaf(w.y, sr, w.x * si);
            sr = nr; si = ni;
        }
        st[wid][lane] = make_float2(sr, si);
    }
    __syncthreads();

    if (wid == 0) {   // cross-chunk scan
        float2 wc = g_wC[h * NM + lane];
        float cr = 0.f, ci = 0.f;
        #pragma unroll
        for (int jc = 0; jc < NCHK; jc++) {
            sinit[jc][lane] = make_float2(cr, ci);
            float2 b = st[jc][lane];
            float nr = fmaf(wc.x, cr, fmaf(-wc.y, ci, b.x));
            float ni = fmaf(wc.y, cr, fmaf(wc.x, ci, b.y));
            cr = nr; ci = ni;
        }
    }
    __syncthreads();

    {   // Pass C: re-scan with true init; 3-round butterfly; 4 partials to smem
        float2 s0 = sinit[wid][lane];
        float sr = s0.x, si = s0.y;
        int base = wid * CHK;
        #pragma unroll 4
        for (int j = 0; j < CHK; j++) {
            float zv = zs[base + j];
            float nr = fmaf(w.x, sr, fmaf(-w.y, si, zv));
            float ni = fmaf(w.y, sr, w.x * si);
            sr = nr; si = ni;
            float v = fmaf(c.x, nr, -c.y * ni);
            v += __shfl_xor_sync(0xffffffffu, v, 16);
            v += __shfl_xor_sync(0xffffffffu, v, 8);
            v += __shfl_xor_sync(0xffffffffu, v, 4);
            if (lane < 4) vbuf[wid][j][lane] = v;
        }
    }
    float Dh = Dsk[h];
    __syncthreads();

    // epilogue: sum partials, + D*z, gelu, write bf16 hi/lo B row (k = h)
    __nv_bfloat16* bh = g_Bhi + h * LSEQ;
    __nv_bfloat16* bl = g_Blo + h * LSEQ;
    const float* vflat = &vbuf[0][0][0];
    for (int i = tid; i < LSEQ; i += 512) {
        float4 p = *reinterpret_cast<const float4*>(vflat + i * 4);
        float y  = (p.x + p.y) + (p.z + p.w);
        float x  = fmaf(Dh, zs[i], y);
        float x3 = x * x * x;
        float t  = tanhf(0.7978845608028654f * fmaf(0.044715f, x3, x));
        float gl = 0.5f * x * (1.f + t);
        __nv_bfloat16 hi = __float2bfloat16(gl);
        bh[i] = hi;
        bl[i] = __float2bfloat16(gl - __bfloat162float(hi));
    }
}

// ---------------- HMMA GEMM: Y2[1022,2048] = A @ B (split-bf16, mma.sync) --------
// A [m][k] row-major; B [k][n] K-major (ldmatrix.trans). 3 segments.

__device__ __forceinline__ void cp16(uint32_t saddr, const void* gptr) {
    asm volatile("cp.async.ca.shared.global [%0], [%1], 16;" :: "r"(saddr), "l"(gptr));
}
__device__ __forceinline__ uint32_t swzA(int row, int ch) {
    return (uint32_t)(row * 64 + ((ch ^ ((row >> 1) & 3)) << 4));
}
__device__ __forceinline__ uint32_t swzB(int row, int ch) {
    return (uint32_t)(row * 128 + ((ch ^ (row & 7)) << 4));
}

__global__ __launch_bounds__(256, 2) void gemm_hmma_kernel() {
    __shared__ __align__(128) char sA[2][8192];   // 128 m x 32 k bf16
    __shared__ __align__(128) char sB[2][4096];   // 32 k x 64 n bf16

    const int t    = threadIdx.x;
    const int wid  = t >> 5;
    const int lane = t & 31;
    const int n0   = blockIdx.x * 64;
    const int m0   = blockIdx.y * 128;
    const int wm   = (wid & 1) * 64;
    const int wn   = (wid >> 1) * 16;

    const uint32_t sAu = (uint32_t)__cvta_generic_to_shared(&sA[0][0]);
    const uint32_t sBu = (uint32_t)__cvta_generic_to_shared(&sB[0][0]);

    // A load slots: 2 rows/thread
    const int arow0 = t >> 2, ach = t & 3;
    const int arow1 = arow0 + 64;
    const uint32_t aso0 = swzA(arow0, ach);
    const uint32_t aso1 = swzA(arow1, ach);
    // B load slots: 1 slot/thread
    const int brow = t >> 3, bch = t & 7;
    const uint32_t bso = swzB(brow, bch);

    // ldmatrix lane geometry
    const int ra = lane & 15;             // A row within 16
    const int ca = lane >> 4;             // A k-half chunk
    const int bg = lane >> 3;             // B group 0..3
    const int br = lane & 7;              // B row within 8

    const __nv_bfloat16* Asegs[3] = {g_Ahi, g_Ahi, g_Alo};
    const __nv_bfloat16* Bsegs[3] = {g_Bhi, g_Blo, g_Bhi};

    float acc[4][2][4];
    #pragma unroll
    for (int i = 0; i < 4; i++)
        #pragma unroll
        for (int j = 0; j < 2; j++)
            #pragma unroll
            for (int q = 0; q < 4; q++) acc[i][j][q] = 0.f;

    {   // prologue chunk 0
        const __nv_bfloat16* Ap = Asegs[0];
        const __nv_bfloat16* Bp = Bsegs[0];
        cp16(sAu + aso0, Ap + (m0 + arow0) * KPAD + ach * 8);
        cp16(sAu + aso1, Ap + (m0 + arow1) * KPAD + ach * 8);
        cp16(sBu + bso, Bp + brow * LSEQ + n0 + bch * 8);
        asm volatile("cp.async.commit_group;" ::: "memory");
    }

    for (int it = 0; it < 48; it++) {
        const int buf = it & 1;
        const uint32_t sAb = sAu + buf * 8192;
        const uint32_t sBb = sBu + buf * 4096;

        if (it + 1 < 48) {
            const int nit = it + 1;
            const int seg = nit >> 4, kc = nit & 15;
            const __nv_bfloat16* Ap = Asegs[seg];
            const __nv_bfloat16* Bp = Bsegs[seg];
            const uint32_t dA = sAu + (nit & 1) * 8192;
            const uint32_t dB = sBu + (nit & 1) * 4096;
            cp16(dA + aso0, Ap + (m0 + arow0) * KPAD + kc * 32 + ach * 8);
            cp16(dA + aso1, Ap + (m0 + arow1) * KPAD + kc * 32 + ach * 8);
            cp16(dB + bso, Bp + (kc * 32 + brow) * LSEQ + n0 + bch * 8);
            asm volatile("cp.async.commit_group;" ::: "memory");
            asm volatile("cp.async.wait_group 1;" ::: "memory");
        } else {
            asm volatile("cp.async.wait_group 0;" ::: "memory");
        }
        __syncthreads();

        #pragma unroll
        for (int ks = 0; ks < 2; ks++) {
            uint32_t a[4][4], b[2][2];
            #pragma unroll
            for (int mt = 0; mt < 4; mt++) {
                uint32_t ad = sAb + swzA(wm + mt * 16 + ra, ks * 2 + ca);
                asm volatile("ldmatrix.sync.aligned.m8n8.x4.shared.b16 {%0,%1,%2,%3}, [%4];"
                             : "=r"(a[mt][0]), "=r"(a[mt][1]), "=r"(a[mt][2]), "=r"(a[mt][3])
                             : "r"(ad));
            }
            {   // B: one x4.trans covers k16 x n16 for this warp
                int krow = ks * 16 + (bg & 1) * 8 + br;
                int nch  = (wn >> 3) + (bg >> 1);
                uint32_t bd = sBb + swzB(krow, nch);
                uint32_t r0, r1, r2, r3;
                asm volatile("ldmatrix.sync.aligned.m8n8.x4.trans.shared.b16 {%0,%1,%2,%3}, [%4];"
                             : "=r"(r0), "=r"(r1), "=r"(r2), "=r"(r3) : "r"(bd));
                b[0][0] = r0; b[0][1] = r1;
                b[1][0] = r2; b[1][1] = r3;
            }
            #pragma unroll
            for (int mt = 0; mt < 4; mt++)
                #pragma unroll
                for (int nt = 0; nt < 2; nt++) {
                    asm volatile(
                        "mma.sync.aligned.m16n8k16.row.col.f32.bf16.bf16.f32 "
                        "{%0,%1,%2,%3}, {%4,%5,%6,%7}, {%8,%9}, {%0,%1,%2,%3};"
                        : "+f"(acc[mt][nt][0]), "+f"(acc[mt][nt][1]),
                          "+f"(acc[mt][nt][2]), "+f"(acc[mt][nt][3])
                        : "r"(a[mt][0]), "r"(a[mt][1]), "r"(a[mt][2]), "r"(a[mt][3]),
                          "r"(b[nt][0]), "r"(b[nt][1]));
                }
        }
        __syncthreads();
    }

    #pragma unroll
    for (int mt = 0; mt < 4; mt++) {
        int mr0 = m0 + wm + mt * 16 + (lane >> 2);
        #pragma unroll
        for (int nt = 0; nt < 2; nt++) {
            int nc = n0 + wn + nt * 8 + (lane & 3) * 2;
            if (mr0 < TWOH)
                *reinterpret_cast<float2*>(&g_Y2[mr0 * LSEQ + nc]) =
                    make_float2(acc[mt][nt][0], acc[mt][nt][1]);
            if (mr0 + 8 < TWOH)
                *reinterpret_cast<float2*>(&g_Y2[(mr0 + 8) * LSEQ + nc]) =
                    make_float2(acc[mt][nt][2], acc[mt][nt][3]);
        }
    }
}

// ---------------- GLU + bias + residual + channel LayerNorm ----------------
__global__ __launch_bounds__(512) void lnglu_kernel(const float* __restrict__ Zext,
                                                    const float* __restrict__ gb,
                                                    const float* __restrict__ lng,
                                                    const float* __restrict__ lnb,
                                                    float* __restrict__ ext_out,
                                                    int src, int dst) {
    const float* res = zsrc_ptr(src, Zext);
    float* outp = dst < 0 ? ext_out : (dst == 0 ? g_Za : g_Zb);
    int tx = threadIdx.x & 15;          // column within 16-wide tile
    int hg = threadIdx.x >> 4;          // 0..31
    int l  = blockIdx.x * 16 + tx;      // grid 128

    float s1 = 0.f, s2 = 0.f;
    for (int h = hg; h < HCH; h += 32) {
        float a = g_Y2[h * LSEQ + l] + gb[h];
        float b = g_Y2[(h + HCH) * LSEQ + l] + gb[h + HCH];
        float g = a / (1.f + __expf(-b)) + res[h * LSEQ + l];
        s1 += g; s2 += g * g;
    }
    __shared__ float r1[32][17], r2[32][17];
    __shared__ float mu_s[16], rs_s[16];
    r1[hg][tx] = s1; r2[hg][tx] = s2;
    __syncthreads();
    if (threadIdx.x < 16) {
        float a1 = 0.f, a2 = 0.f;
        #pragma unroll
        for (int j = 0; j < 32; j++) { a1 += r1[j][threadIdx.x]; a2 += r2[j][threadIdx.x]; }
        float mu  = a1 * (1.f / (float)HCH);
        float var = a2 * (1.f / (float)HCH) - mu * mu;
        mu_s[threadIdx.x] = mu;
        rs_s[threadIdx.x] = rsqrtf(var + 1e-5f);
    }
    __syncthreads();
    float mu = mu_s[tx], rs = rs_s[tx];
    for (int h = hg; h < HCH; h += 32) {
        float a = g_Y2[h * LSEQ + l] + gb[h];
        float b = g_Y2[(h + HCH) * LSEQ + l] + gb[h + HCH];
        float g = a / (1.f + __expf(-b)) + res[h * LSEQ + l];
        outp[h * LSEQ + l] = (g - mu) * rs * lng[h] + lnb[h];
    }
}

// ---------------- launch ----------------
extern "C" void kernel_launch(void* const* d_in, const int* in_sizes, int n_in,
                              void* d_out, int out_size) {
    const float* Z      = (const float*)d_in[0];
    const float* log_dt = (const float*)d_in[1];
    const float* Arl    = (const float*)d_in[2];
    const float* Aim    = (const float*)d_in[3];
    const float* Cre    = (const float*)d_in[4];
    const float* Cim    = (const float*)d_in[5];
    const float* Dsk    = (const float*)d_in[6];
    const float* gw     = (const float*)d_in[7];
    const float* gb     = (const float*)d_in[8];
    const float* lng    = (const float*)d_in[9];
    const float* lnb    = (const float*)d_in[10];
    float* out = (float*)d_out;

    kprep_kernel<<<(HCH * NM + 255) / 256, 256>>>(log_dt, Arl, Aim, Cre, Cim);
    asplit_kernel<<<(MPAD * KPAD) / 256, 256>>>(gw);

    const int srcs[4] = {-1, 0, 1, 0};
    const int dsts[4] = { 0, 1, 0, -1};
    for (int layer = 0; layer < 4; ++layer) {
        conv_kernel<<<HCH, 512>>>(Z, Dsk, srcs[layer]);
        gemm_hmma_kernel<<<dim3(32, 8), 256>>>();
        lnglu_kernel<<<128, 512>>>(Z, gb, lng, lnb, out, srcs[layer], dsts[layer]);
    }
}

// round 6
// speedup vs baseline: 1.4266x; 1.0684x over previous
#include <cuda_runtime.h>
#include <cuda_bf16.h>
#include <math.h>
#include <stdint.h>

#define HCH 511
#define LSEQ 2048
#define NM 32
#define CHK 128
#define NCHK 16
#define KPAD 512
#define MPAD 1024
#define TWOH 1022

// ---------------- scratch (device globals) ----------------
__device__ float2 g_w [HCH * NM];
__device__ float2 g_c2[HCH * NM];
__device__ float2 g_wC[HCH * NM];
__device__ float  g_Y2[TWOH * LSEQ];            // GEMM output
__device__ float  g_Za[HCH * LSEQ];             // ping-pong activations
__device__ float  g_Zb[HCH * LSEQ];
__device__ __nv_bfloat16 g_Ahi[MPAD * KPAD];    // weight split, [m][k], zero padded
__device__ __nv_bfloat16 g_Alo[MPAD * KPAD];
__device__ __nv_bfloat16 g_Bhi[KPAD * LSEQ];    // activation split, K-major [k][n]
__device__ __nv_bfloat16 g_Blo[KPAD * LSEQ];

__device__ __forceinline__ const float* zsrc_ptr(int sel, const float* ext) {
    return sel < 0 ? ext : (sel == 0 ? g_Za : g_Zb);
}

// ---------------- prep: per-mode discretized SSM constants ----------------
__global__ void kprep_kernel(const float* __restrict__ log_dt, const float* __restrict__ Arl,
                             const float* __restrict__ Aim, const float* __restrict__ Cre,
                             const float* __restrict__ Cim) {
    int idx = blockIdx.x * blockDim.x + threadIdx.x;
    if (idx >= HCH * NM) return;
    int h = idx >> 5;
    float dt  = expf(log_dt[h]);
    float Ar  = -expf(Arl[idx]);
    float Ai  = Aim[idx];
    float dar = Ar * dt, dai = Ai * dt;
    float er  = expf(dar);
    float wr  = er * cosf(dai);
    float wi  = er * sinf(dai);
    float e1r = wr - 1.f, e1i = wi;
    float inv = 1.f / (Ar * Ar + Ai * Ai);
    float fr  = (e1r * Ar + e1i * Ai) * inv;
    float fi  = (e1i * Ar - e1r * Ai) * inv;
    float cr  = Cre[idx] * fr - Cim[idx] * fi;
    float ci  = Cre[idx] * fi + Cim[idx] * fr;
    g_w[idx]  = make_float2(wr, wi);
    g_c2[idx] = make_float2(2.f * cr, 2.f * ci);
    double ph = (double)dai * (double)CHK;
    double sv, cv;
    sincos(ph, &sv, &cv);
    double eC = exp((double)dar * (double)CHK);
    g_wC[idx] = make_float2((float)(eC * cv), (float)(eC * sv));
}

// ---------------- prep: split glu_w into bf16 hi/lo; zero pad rows --------------
__global__ void asplit_kernel(const float* __restrict__ gw) {
    int idx = blockIdx.x * blockDim.x + threadIdx.x;   // 0 .. 1024*512-1
    int m = idx >> 9;
    int k = idx & 511;
    float v = (m < TWOH && k < HCH) ? gw[m * HCH + k] : 0.f;
    __nv_bfloat16 hi = __float2bfloat16(v);
    g_Ahi[idx] = hi;
    g_Alo[idx] = __float2bfloat16(v - __bfloat162float(hi));
    if (idx < LSEQ) {   // zero the k=511 pad row of B
        g_Bhi[HCH * LSEQ + idx] = __float2bfloat16(0.f);
        g_Blo[HCH * LSEQ + idx] = __float2bfloat16(0.f);
    }
}

// ---------------- conv: chunked parallel scan; writes bf16-split B rows ----------
__global__ __launch_bounds__(512) void conv_kernel(const float* __restrict__ Zext,
                                                   const float* __restrict__ Dsk, int src) {
    __shared__ float  zs[LSEQ];
    __shared__ float  vbuf[NCHK][CHK][4];
    __shared__ float2 st[NCHK][NM];
    __shared__ float2 sinit[NCHK][NM];
    int h    = blockIdx.x;
    int tid  = threadIdx.x;
    int wid  = tid >> 5;
    int lane = tid & 31;
    const float* zrow = zsrc_ptr(src, Zext) + h * LSEQ;
    for (int i = tid; i < LSEQ; i += 512) zs[i] = zrow[i];
    float2 w = g_w[h * NM + lane];
    float2 c = g_c2[h * NM + lane];
    __syncthreads();

    {   // Pass A: per-chunk local final state (zero init)
        float sr = 0.f, si = 0.f;
        int base = wid * CHK;
        #pragma unroll 8
        for (int j = 0; j < CHK; j++) {
            float zv = zs[base + j];
            float nr = fmaf(w.x, sr, fmaf(-w.y, si, zv));
            float ni = fmaf(w.y, sr, w.x * si);
            sr = nr; si = ni;
        }
        st[wid][lane] = make_float2(sr, si);
    }
    __syncthreads();

    if (wid == 0) {   // cross-chunk scan
        float2 wc = g_wC[h * NM + lane];
        float cr = 0.f, ci = 0.f;
        #pragma unroll
        for (int jc = 0; jc < NCHK; jc++) {
            sinit[jc][lane] = make_float2(cr, ci);
            float2 b = st[jc][lane];
            float nr = fmaf(wc.x, cr, fmaf(-wc.y, ci, b.x));
            float ni = fmaf(wc.y, cr, fmaf(wc.x, ci, b.y));
            cr = nr; ci = ni;
        }
    }
    __syncthreads();

    {   // Pass C: re-scan with true init; 3-round butterfly; 4 partials to smem
        float2 s0 = sinit[wid][lane];
        float sr = s0.x, si = s0.y;
        int base = wid * CHK;
        #pragma unroll 4
        for (int j = 0; j < CHK; j++) {
            float zv = zs[base + j];
            float nr = fmaf(w.x, sr, fmaf(-w.y, si, zv));
            float ni = fmaf(w.y, sr, w.x * si);
            sr = nr; si = ni;
            float v = fmaf(c.x, nr, -c.y * ni);
            v += __shfl_xor_sync(0xffffffffu, v, 16);
            v += __shfl_xor_sync(0xffffffffu, v, 8);
            v += __shfl_xor_sync(0xffffffffu, v, 4);
            if (lane < 4) vbuf[wid][j][lane] = v;
        }
    }
    float Dh = Dsk[h];
    __syncthreads();

    // epilogue: sum partials, + D*z, gelu, write bf16 hi/lo B row (k = h)
    __nv_bfloat16* bh = g_Bhi + h * LSEQ;
    __nv_bfloat16* bl = g_Blo + h * LSEQ;
    const float* vflat = &vbuf[0][0][0];
    for (int i = tid; i < LSEQ; i += 512) {
        float4 p = *reinterpret_cast<const float4*>(vflat + i * 4);
        float y  = (p.x + p.y) + (p.z + p.w);
        float x  = fmaf(Dh, zs[i], y);
        float x3 = x * x * x;
        float t  = tanhf(0.7978845608028654f * fmaf(0.044715f, x3, x));
        float gl = 0.5f * x * (1.f + t);
        __nv_bfloat16 hi = __float2bfloat16(gl);
        bh[i] = hi;
        bl[i] = __float2bfloat16(gl - __bfloat162float(hi));
    }
}

// ---------------- HMMA GEMM: Y2[1022,2048] = A @ B (split-bf16, mma.sync) --------
// Tile 128x128, BK=32, 3-stage cp.async pipeline, warp tile 64x32 (8 warps 2x4).
// A [m][k] row-major; B [k][n] K-major (ldmatrix.trans). 3 K-segments of 512.

__device__ __forceinline__ void cp16(uint32_t saddr, const void* gptr) {
    asm volatile("cp.async.ca.shared.global [%0], [%1], 16;" :: "r"(saddr), "l"(gptr));
}
__device__ __forceinline__ uint32_t swzA(int row, int ch) {   // 64B rows, 4 chunks
    return (uint32_t)(row * 64 + ((ch ^ ((row >> 1) & 3)) << 4));
}
__device__ __forceinline__ uint32_t swzB(int row, int ch) {   // 256B rows, 16 chunks
    return (uint32_t)(row * 256 + ((ch ^ (row & 7)) << 4));
}

__global__ __launch_bounds__(256) void gemm_hmma_kernel() {
    __shared__ __align__(128) char sA[3][8192];   // 128 m x 32 k bf16
    __shared__ __align__(128) char sB[3][8192];   // 32 k x 128 n bf16

    const int t    = threadIdx.x;
    const int wid  = t >> 5;
    const int lane = t & 31;
    const int n0   = blockIdx.x * 128;
    const int m0   = blockIdx.y * 128;
    const int wm   = (wid & 1) * 64;
    const int wn   = (wid >> 1) * 32;

    const uint32_t sAu = (uint32_t)__cvta_generic_to_shared(&sA[0][0]);
    const uint32_t sBu = (uint32_t)__cvta_generic_to_shared(&sB[0][0]);

    // A load slots: 2 rows/thread (rows t>>2 and +64, chunk t&3)
    const int arow0 = t >> 2, ach = t & 3;
    const int arow1 = arow0 + 64;
    const uint32_t aso0 = swzA(arow0, ach);
    const uint32_t aso1 = swzA(arow1, ach);
    // B load slots: 2 slots/thread (slots t and t+256; row = slot>>4, chunk = slot&15)
    const int brow0 = t >> 4,        bch0 = t & 15;
    const int brow1 = (t + 256) >> 4, bch1 = t & 15;
    const uint32_t bso0 = swzB(brow0, bch0);
    const uint32_t bso1 = swzB(brow1, bch1);

    // ldmatrix lane geometry
    const int ra = lane & 15;             // A row within 16
    const int ca = lane >> 4;             // A k-half chunk
    const int bg = lane >> 3;             // B matrix id 0..3
    const int br = lane & 7;              // B row within 8

    const __nv_bfloat16* Asegs[3] = {g_Ahi, g_Ahi, g_Alo};
    const __nv_bfloat16* Bsegs[3] = {g_Bhi, g_Blo, g_Bhi};

    float acc[4][4][4];
    #pragma unroll
    for (int i = 0; i < 4; i++)
        #pragma unroll
        for (int j = 0; j < 4; j++)
            #pragma unroll
            for (int q = 0; q < 4; q++) acc[i][j][q] = 0.f;

    // prologue: stages 0 and 1
    #pragma unroll
    for (int st = 0; st < 2; st++) {
        const int seg = st >> 4, kc = st & 15;
        const __nv_bfloat16* Ap = Asegs[seg];
        const __nv_bfloat16* Bp = Bsegs[seg];
        const uint32_t dA = sAu + st * 8192;
        const uint32_t dB = sBu + st * 8192;
        cp16(dA + aso0, Ap + (m0 + arow0) * KPAD + kc * 32 + ach * 8);
        cp16(dA + aso1, Ap + (m0 + arow1) * KPAD + kc * 32 + ach * 8);
        cp16(dB + bso0, Bp + (kc * 32 + brow0) * LSEQ + n0 + bch0 * 8);
        cp16(dB + bso1, Bp + (kc * 32 + brow1) * LSEQ + n0 + bch1 * 8);
        asm volatile("cp.async.commit_group;" ::: "memory");
    }

    for (int it = 0; it < 48; it++) {
        const int buf = it % 3;
        const uint32_t sAb = sAu + buf * 8192;
        const uint32_t sBb = sBu + buf * 8192;

        asm volatile("cp.async.wait_group 1;" ::: "memory");
        __syncthreads();

        #pragma unroll
        for (int ks = 0; ks < 2; ks++) {
            uint32_t a[4][4], b[4][2];
            #pragma unroll
            for (int mt = 0; mt < 4; mt++) {
                uint32_t ad = sAb + swzA(wm + mt * 16 + ra, ks * 2 + ca);
                asm volatile("ldmatrix.sync.aligned.m8n8.x4.shared.b16 {%0,%1,%2,%3}, [%4];"
                             : "=r"(a[mt][0]), "=r"(a[mt][1]), "=r"(a[mt][2]), "=r"(a[mt][3])
                             : "r"(ad));
            }
            #pragma unroll
            for (int nh = 0; nh < 2; nh++) {   // two n16 halves of the warp's n32
                int krow = ks * 16 + (bg & 1) * 8 + br;
                int nch  = (wn >> 3) + nh * 2 + (bg >> 1);
                uint32_t bd = sBb + swzB(krow, nch);
                uint32_t r0, r1, r2, r3;
                asm volatile("ldmatrix.sync.aligned.m8n8.x4.trans.shared.b16 {%0,%1,%2,%3}, [%4];"
                             : "=r"(r0), "=r"(r1), "=r"(r2), "=r"(r3) : "r"(bd));
                b[nh * 2][0] = r0;     b[nh * 2][1] = r1;
                b[nh * 2 + 1][0] = r2; b[nh * 2 + 1][1] = r3;
            }
            #pragma unroll
            for (int mt = 0; mt < 4; mt++)
                #pragma unroll
                for (int nt = 0; nt < 4; nt++) {
                    asm volatile(
                        "mma.sync.aligned.m16n8k16.row.col.f32.bf16.bf16.f32 "
                        "{%0,%1,%2,%3}, {%4,%5,%6,%7}, {%8,%9}, {%0,%1,%2,%3};"
                        : "+f"(acc[mt][nt][0]), "+f"(acc[mt][nt][1]),
                          "+f"(acc[mt][nt][2]), "+f"(acc[mt][nt][3])
                        : "r"(a[mt][0]), "r"(a[mt][1]), "r"(a[mt][2]), "r"(a[mt][3]),
                          "r"(b[nt][0]), "r"(b[nt][1]));
                }
        }

        // issue stage it+2 into buffer (it+2)%3 (safe: all warps are past compute(it-1))
        if (it + 2 < 48) {
            const int nit = it + 2;
            const int seg = nit >> 4, kc = nit & 15;
            const __nv_bfloat16* Ap = Asegs[seg];
            const __nv_bfloat16* Bp = Bsegs[seg];
            const uint32_t dA = sAu + (nit % 3) * 8192;
            const uint32_t dB = sBu + (nit % 3) * 8192;
            cp16(dA + aso0, Ap + (m0 + arow0) * KPAD + kc * 32 + ach * 8);
            cp16(dA + aso1, Ap + (m0 + arow1) * KPAD + kc * 32 + ach * 8);
            cp16(dB + bso0, Bp + (kc * 32 + brow0) * LSEQ + n0 + bch0 * 8);
            cp16(dB + bso1, Bp + (kc * 32 + brow1) * LSEQ + n0 + bch1 * 8);
        }
        asm volatile("cp.async.commit_group;" ::: "memory");
    }

    #pragma unroll
    for (int mt = 0; mt < 4; mt++) {
        int mr0 = m0 + wm + mt * 16 + (lane >> 2);
        #pragma unroll
        for (int nt = 0; nt < 4; nt++) {
            int nc = n0 + wn + nt * 8 + (lane & 3) * 2;
            if (mr0 < TWOH)
                *reinterpret_cast<float2*>(&g_Y2[mr0 * LSEQ + nc]) =
                    make_float2(acc[mt][nt][0], acc[mt][nt][1]);
            if (mr0 + 8 < TWOH)
                *reinterpret_cast<float2*>(&g_Y2[(mr0 + 8) * LSEQ + nc]) =
                    make_float2(acc[mt][nt][2], acc[mt][nt][3]);
        }
    }
}

// ---------------- GLU + bias + residual + channel LayerNorm ----------------
__global__ __launch_bounds__(512) void lnglu_kernel(const float* __restrict__ Zext,
                                                    const float* __restrict__ gb,
                                                    const float* __restrict__ lng,
                                                    const float* __restrict__ lnb,
                                                    float* __restrict__ ext_out,
                                                    int src, int dst) {
    const float* res = zsrc_ptr(src, Zext);
    float* outp = dst < 0 ? ext_out : (dst == 0 ? g_Za : g_Zb);
    int tx = threadIdx.x & 15;          // column within 16-wide tile
    int hg = threadIdx.x >> 4;          // 0..31
    int l  = blockIdx.x * 16 + tx;      // grid 128

    float s1 = 0.f, s2 = 0.f;
    for (int h = hg; h < HCH; h += 32) {
        float a = g_Y2[h * LSEQ + l] + gb[h];
        float b = g_Y2[(h + HCH) * LSEQ + l] + gb[h + HCH];
        float g = a / (1.f + __expf(-b)) + res[h * LSEQ + l];
        s1 += g; s2 += g * g;
    }
    __shared__ float r1[32][17], r2[32][17];
    __shared__ float mu_s[16], rs_s[16];
    r1[hg][tx] = s1; r2[hg][tx] = s2;
    __syncthreads();
    if (threadIdx.x < 16) {
        float a1 = 0.f, a2 = 0.f;
        #pragma unroll
        for (int j = 0; j < 32; j++) { a1 += r1[j][threadIdx.x]; a2 += r2[j][threadIdx.x]; }
        float mu  = a1 * (1.f / (float)HCH);
        float var = a2 * (1.f / (float)HCH) - mu * mu;
        mu_s[threadIdx.x] = mu;
        rs_s[threadIdx.x] = rsqrtf(var + 1e-5f);
    }
    __syncthreads();
    float mu = mu_s[tx], rs = rs_s[tx];
    for (int h = hg; h < HCH; h += 32) {
        float a = g_Y2[h * LSEQ + l] + gb[h];
        float b = g_Y2[(h + HCH) * LSEQ + l] + gb[h + HCH];
        float g = a / (1.f + __expf(-b)) + res[h * LSEQ + l];
        outp[h * LSEQ + l] = (g - mu) * rs * lng[h] + lnb[h];
    }
}

// ---------------- launch ----------------
extern "C" void kernel_launch(void* const* d_in, const int* in_sizes, int n_in,
                              void* d_out, int out_size) {
    const float* Z      = (const float*)d_in[0];
    const float* log_dt = (const float*)d_in[1];
    const float* Arl    = (const float*)d_in[2];
    const float* Aim    = (const float*)d_in[3];
    const float* Cre    = (const float*)d_in[4];
    const float* Cim    = (const float*)d_in[5];
    const float* Dsk    = (const float*)d_in[6];
    const float* gw     = (const float*)d_in[7];
    const float* gb     = (const float*)d_in[8];
    const float* lng    = (const float*)d_in[9];
    const float* lnb    = (const float*)d_in[10];
    float* out = (float*)d_out;

    kprep_kernel<<<(HCH * NM + 255) / 256, 256>>>(log_dt, Arl, Aim, Cre, Cim);
    asplit_kernel<<<(MPAD * KPAD) / 256, 256>>>(gw);

    const int srcs[4] = {-1, 0, 1, 0};
    const int dsts[4] = { 0, 1, 0, -1};
    for (int layer = 0; layer < 4; ++layer) {
        conv_kernel<<<HCH, 512>>>(Z, Dsk, srcs[layer]);
        gemm_hmma_kernel<<<dim3(16, 8), 256>>>();
        lnglu_kernel<<<128, 512>>>(Z, gb, lng, lnb, out, srcs[layer], dsts[layer]);
    }
}

// round 7
// speedup vs baseline: 1.6526x; 1.1584x over previous
#include <cuda_runtime.h>
#include <cuda_bf16.h>
#include <math.h>
#include <stdint.h>

#define HCH 511
#define LSEQ 2048
#define NM 32
#define CHK 128
#define NCHK 16
#define KPAD 512
#define MPAD 1024
#define TWOH 1022

// ---------------- scratch (device globals) ----------------
__device__ float2 g_w [HCH * NM];
__device__ float2 g_c2[HCH * NM];
__device__ float2 g_wC[HCH * NM];
__device__ float  g_Y2p[3][TWOH * LSEQ];        // split-K partial GEMM outputs
__device__ float  g_Za[HCH * LSEQ];             // ping-pong activations
__device__ float  g_Zb[HCH * LSEQ];
__device__ __nv_bfloat16 g_Ahi[MPAD * KPAD];    // weight split, [m][k], zero padded
__device__ __nv_bfloat16 g_Alo[MPAD * KPAD];
__device__ __nv_bfloat16 g_Bhi[KPAD * LSEQ];    // activation split, K-major [k][n]
__device__ __nv_bfloat16 g_Blo[KPAD * LSEQ];

__device__ __forceinline__ const float* zsrc_ptr(int sel, const float* ext) {
    return sel < 0 ? ext : (sel == 0 ? g_Za : g_Zb);
}

// ---------------- prep: per-mode discretized SSM constants ----------------
__global__ void kprep_kernel(const float* __restrict__ log_dt, const float* __restrict__ Arl,
                             const float* __restrict__ Aim, const float* __restrict__ Cre,
                             const float* __restrict__ Cim) {
    int idx = blockIdx.x * blockDim.x + threadIdx.x;
    if (idx >= HCH * NM) return;
    int h = idx >> 5;
    float dt  = expf(log_dt[h]);
    float Ar  = -expf(Arl[idx]);
    float Ai  = Aim[idx];
    float dar = Ar * dt, dai = Ai * dt;
    float er  = expf(dar);
    float wr  = er * cosf(dai);
    float wi  = er * sinf(dai);
    float e1r = wr - 1.f, e1i = wi;
    float inv = 1.f / (Ar * Ar + Ai * Ai);
    float fr  = (e1r * Ar + e1i * Ai) * inv;
    float fi  = (e1i * Ar - e1r * Ai) * inv;
    float cr  = Cre[idx] * fr - Cim[idx] * fi;
    float ci  = Cre[idx] * fi + Cim[idx] * fr;
    g_w[idx]  = make_float2(wr, wi);
    g_c2[idx] = make_float2(2.f * cr, 2.f * ci);
    double ph = (double)dai * (double)CHK;
    double sv, cv;
    sincos(ph, &sv, &cv);
    double eC = exp((double)dar * (double)CHK);
    g_wC[idx] = make_float2((float)(eC * cv), (float)(eC * sv));
}

// ---------------- prep: split glu_w into bf16 hi/lo; zero pad rows --------------
__global__ void asplit_kernel(const float* __restrict__ gw) {
    int idx = blockIdx.x * blockDim.x + threadIdx.x;   // 0 .. 1024*512-1
    int m = idx >> 9;
    int k = idx & 511;
    float v = (m < TWOH && k < HCH) ? gw[m * HCH + k] : 0.f;
    __nv_bfloat16 hi = __float2bfloat16(v);
    g_Ahi[idx] = hi;
    g_Alo[idx] = __float2bfloat16(v - __bfloat162float(hi));
    if (idx < LSEQ) {   // zero the k=511 pad row of B
        g_Bhi[HCH * LSEQ + idx] = __float2bfloat16(0.f);
        g_Blo[HCH * LSEQ + idx] = __float2bfloat16(0.f);
    }
}

// ---------------- conv: chunked parallel scan; writes bf16-split B rows ----------
__global__ __launch_bounds__(512) void conv_kernel(const float* __restrict__ Zext,
                                                   const float* __restrict__ Dsk, int src) {
    __shared__ float  zs[LSEQ];
    __shared__ float  vbuf[NCHK][CHK][4];
    __shared__ float2 st[NCHK][NM];
    __shared__ float2 sinit[NCHK][NM];
    int h    = blockIdx.x;
    int tid  = threadIdx.x;
    int wid  = tid >> 5;
    int lane = tid & 31;
    const float* zrow = zsrc_ptr(src, Zext) + h * LSEQ;
    for (int i = tid; i < LSEQ; i += 512) zs[i] = zrow[i];
    float2 w = g_w[h * NM + lane];
    float2 c = g_c2[h * NM + lane];
    __syncthreads();

    {   // Pass A: per-chunk local final state (zero init)
        float sr = 0.f, si = 0.f;
        int base = wid * CHK;
        #pragma unroll 8
        for (int j = 0; j < CHK; j++) {
            float zv = zs[base + j];
            float nr = fmaf(w.x, sr, fmaf(-w.y, si, zv));
            float ni = fmaf(w.y, sr, w.x * si);
            sr = nr; si = ni;
        }
        st[wid][lane] = make_float2(sr, si);
    }
    __syncthreads();

    if (wid == 0) {   // cross-chunk scan
        float2 wc = g_wC[h * NM + lane];
        float cr = 0.f, ci = 0.f;
        #pragma unroll
        for (int jc = 0; jc < NCHK; jc++) {
            sinit[jc][lane] = make_float2(cr, ci);
            float2 b = st[jc][lane];
            float nr = fmaf(wc.x, cr, fmaf(-wc.y, ci, b.x));
            float ni = fmaf(wc.y, cr, fmaf(wc.x, ci, b.y));
            cr = nr; ci = ni;
        }
    }
    __syncthreads();

    {   // Pass C: re-scan with true init; 3-round butterfly; 4 partials to smem
        float2 s0 = sinit[wid][lane];
        float sr = s0.x, si = s0.y;
        int base = wid * CHK;
        #pragma unroll 4
        for (int j = 0; j < CHK; j++) {
            float zv = zs[base + j];
            float nr = fmaf(w.x, sr, fmaf(-w.y, si, zv));
            float ni = fmaf(w.y, sr, w.x * si);
            sr = nr; si = ni;
            float v = fmaf(c.x, nr, -c.y * ni);
            v += __shfl_xor_sync(0xffffffffu, v, 16);
            v += __shfl_xor_sync(0xffffffffu, v, 8);
            v += __shfl_xor_sync(0xffffffffu, v, 4);
            if (lane < 4) vbuf[wid][j][lane] = v;
        }
    }
    float Dh = Dsk[h];
    __syncthreads();

    // epilogue: sum partials, + D*z, gelu, write bf16 hi/lo B row (k = h)
    __nv_bfloat16* bh = g_Bhi + h * LSEQ;
    __nv_bfloat16* bl = g_Blo + h * LSEQ;
    const float* vflat = &vbuf[0][0][0];
    for (int i = tid; i < LSEQ; i += 512) {
        float4 p = *reinterpret_cast<const float4*>(vflat + i * 4);
        float y  = (p.x + p.y) + (p.z + p.w);
        float x  = fmaf(Dh, zs[i], y);
        float x3 = x * x * x;
        float t  = tanhf(0.7978845608028654f * fmaf(0.044715f, x3, x));
        float gl = 0.5f * x * (1.f + t);
        __nv_bfloat16 hi = __float2bfloat16(gl);
        bh[i] = hi;
        bl[i] = __float2bfloat16(gl - __bfloat162float(hi));
    }
}

// ---------------- HMMA GEMM, split-K x3: P[seg] = Aseg @ Bseg ---------------------
// Tile 128x128, BK=32, 3-stage cp.async pipeline, warp tile 64x32 (8 warps 2x4).

__device__ __forceinline__ void cp16(uint32_t saddr, const void* gptr) {
    asm volatile("cp.async.ca.shared.global [%0], [%1], 16;" :: "r"(saddr), "l"(gptr));
}
__device__ __forceinline__ uint32_t swzA(int row, int ch) {   // 64B rows, 4 chunks
    return (uint32_t)(row * 64 + ((ch ^ ((row >> 1) & 3)) << 4));
}
__device__ __forceinline__ uint32_t swzB(int row, int ch) {   // 256B rows, 16 chunks
    return (uint32_t)(row * 256 + ((ch ^ (row & 7)) << 4));
}

__global__ __launch_bounds__(256, 2) void gemm_hmma_kernel() {
    __shared__ __align__(128) char sA[3][8192];   // 128 m x 32 k bf16
    __shared__ __align__(128) char sB[3][8192];   // 32 k x 128 n bf16

    const int t    = threadIdx.x;
    const int wid  = t >> 5;
    const int lane = t & 31;
    const int n0   = blockIdx.x * 128;
    const int m0   = blockIdx.y * 128;
    const int seg  = blockIdx.z;
    const int wm   = (wid & 1) * 64;
    const int wn   = (wid >> 1) * 32;

    const __nv_bfloat16* Ap = (seg == 2) ? g_Alo : g_Ahi;
    const __nv_bfloat16* Bp = (seg == 1) ? g_Blo : g_Bhi;

    const uint32_t sAu = (uint32_t)__cvta_generic_to_shared(&sA[0][0]);
    const uint32_t sBu = (uint32_t)__cvta_generic_to_shared(&sB[0][0]);

    // A load slots: 2 rows/thread
    const int arow0 = t >> 2, ach = t & 3;
    const int arow1 = arow0 + 64;
    const uint32_t aso0 = swzA(arow0, ach);
    const uint32_t aso1 = swzA(arow1, ach);
    // B load slots: 2 slots/thread
    const int brow0 = t >> 4,         bch0 = t & 15;
    const int brow1 = (t + 256) >> 4, bch1 = t & 15;
    const uint32_t bso0 = swzB(brow0, bch0);
    const uint32_t bso1 = swzB(brow1, bch1);

    // ldmatrix lane geometry
    const int ra = lane & 15;
    const int ca = lane >> 4;
    const int bg = lane >> 3;
    const int br = lane & 7;

    float acc[4][4][4];
    #pragma unroll
    for (int i = 0; i < 4; i++)
        #pragma unroll
        for (int j = 0; j < 4; j++)
            #pragma unroll
            for (int q = 0; q < 4; q++) acc[i][j][q] = 0.f;

    // prologue: stages kc=0,1
    #pragma unroll
    for (int st = 0; st < 2; st++) {
        const uint32_t dA = sAu + st * 8192;
        const uint32_t dB = sBu + st * 8192;
        cp16(dA + aso0, Ap + (m0 + arow0) * KPAD + st * 32 + ach * 8);
        cp16(dA + aso1, Ap + (m0 + arow1) * KPAD + st * 32 + ach * 8);
        cp16(dB + bso0, Bp + (st * 32 + brow0) * LSEQ + n0 + bch0 * 8);
        cp16(dB + bso1, Bp + (st * 32 + brow1) * LSEQ + n0 + bch1 * 8);
        asm volatile("cp.async.commit_group;" ::: "memory");
    }

    for (int it = 0; it < 16; it++) {
        const int buf = it % 3;
        const uint32_t sAb = sAu + buf * 8192;
        const uint32_t sBb = sBu + buf * 8192;

        asm volatile("cp.async.wait_group 1;" ::: "memory");
        __syncthreads();

        #pragma unroll
        for (int ks = 0; ks < 2; ks++) {
            uint32_t a[4][4], b[4][2];
            #pragma unroll
            for (int mt = 0; mt < 4; mt++) {
                uint32_t ad = sAb + swzA(wm + mt * 16 + ra, ks * 2 + ca);
                asm volatile("ldmatrix.sync.aligned.m8n8.x4.shared.b16 {%0,%1,%2,%3}, [%4];"
                             : "=r"(a[mt][0]), "=r"(a[mt][1]), "=r"(a[mt][2]), "=r"(a[mt][3])
                             : "r"(ad));
            }
            #pragma unroll
            for (int nh = 0; nh < 2; nh++) {
                int krow = ks * 16 + (bg & 1) * 8 + br;
                int nch  = (wn >> 3) + nh * 2 + (bg >> 1);
                uint32_t bd = sBb + swzB(krow, nch);
                uint32_t r0, r1, r2, r3;
                asm volatile("ldmatrix.sync.aligned.m8n8.x4.trans.shared.b16 {%0,%1,%2,%3}, [%4];"
                             : "=r"(r0), "=r"(r1), "=r"(r2), "=r"(r3) : "r"(bd));
                b[nh * 2][0] = r0;     b[nh * 2][1] = r1;
                b[nh * 2 + 1][0] = r2; b[nh * 2 + 1][1] = r3;
            }
            #pragma unroll
            for (int mt = 0; mt < 4; mt++)
                #pragma unroll
                for (int nt = 0; nt < 4; nt++) {
                    asm volatile(
                        "mma.sync.aligned.m16n8k16.row.col.f32.bf16.bf16.f32 "
                        "{%0,%1,%2,%3}, {%4,%5,%6,%7}, {%8,%9}, {%0,%1,%2,%3};"
                        : "+f"(acc[mt][nt][0]), "+f"(acc[mt][nt][1]),
                          "+f"(acc[mt][nt][2]), "+f"(acc[mt][nt][3])
                        : "r"(a[mt][0]), "r"(a[mt][1]), "r"(a[mt][2]), "r"(a[mt][3]),
                          "r"(b[nt][0]), "r"(b[nt][1]));
                }
        }

        if (it + 2 < 16) {
            const int kc = it + 2;
            const uint32_t dA = sAu + (kc % 3) * 8192;
            const uint32_t dB = sBu + (kc % 3) * 8192;
            cp16(dA + aso0, Ap + (m0 + arow0) * KPAD + kc * 32 + ach * 8);
            cp16(dA + aso1, Ap + (m0 + arow1) * KPAD + kc * 32 + ach * 8);
            cp16(dB + bso0, Bp + (kc * 32 + brow0) * LSEQ + n0 + bch0 * 8);
            cp16(dB + bso1, Bp + (kc * 32 + brow1) * LSEQ + n0 + bch1 * 8);
        }
        asm volatile("cp.async.commit_group;" ::: "memory");
    }

    float* outp = g_Y2p[seg];
    #pragma unroll
    for (int mt = 0; mt < 4; mt++) {
        int mr0 = m0 + wm + mt * 16 + (lane >> 2);
        #pragma unroll
        for (int nt = 0; nt < 4; nt++) {
            int nc = n0 + wn + nt * 8 + (lane & 3) * 2;
            if (mr0 < TWOH)
                *reinterpret_cast<float2*>(&outp[mr0 * LSEQ + nc]) =
                    make_float2(acc[mt][nt][0], acc[mt][nt][1]);
            if (mr0 + 8 < TWOH)
                *reinterpret_cast<float2*>(&outp[(mr0 + 8) * LSEQ + nc]) =
                    make_float2(acc[mt][nt][2], acc[mt][nt][3]);
        }
    }
}

// ---------------- GLU + bias + residual + channel LayerNorm (smem-cached) --------
__global__ __launch_bounds__(512) void lnglu_kernel(const float* __restrict__ Zext,
                                                    const float* __restrict__ gb,
                                                    const float* __restrict__ lng,
                                                    const float* __restrict__ lnb,
                                                    float* __restrict__ ext_out,
                                                    int src, int dst) {
    __shared__ float gsm[HCH * 16];          // cached g values: [h][tx]
    __shared__ float r1[32][17], r2[32][17];
    __shared__ float mu_s[16], rs_s[16];

    const float* res = zsrc_ptr(src, Zext);
    float* outp = dst < 0 ? ext_out : (dst == 0 ? g_Za : g_Zb);
    const float* P0 = g_Y2p[0];
    const float* P1 = g_Y2p[1];
    const float* P2 = g_Y2p[2];
    int tx = threadIdx.x & 15;          // column within 16-wide tile
    int hg = threadIdx.x >> 4;          // 0..31
    int l  = blockIdx.x * 16 + tx;      // grid 128

    float s1 = 0.f, s2 = 0.f;
    for (int h = hg; h < HCH; h += 32) {
        int ia = h * LSEQ + l;
        int ib = (h + HCH) * LSEQ + l;
        float a = (P0[ia] + P1[ia]) + P2[ia] + gb[h];
        float b = (P0[ib] + P1[ib]) + P2[ib] + gb[h + HCH];
        float g = a / (1.f + __expf(-b)) + res[ia];
        gsm[h * 16 + tx] = g;
        s1 += g; s2 += g * g;
    }
    r1[hg][tx] = s1; r2[hg][tx] = s2;
    __syncthreads();
    if (threadIdx.x < 16) {
        float a1 = 0.f, a2 = 0.f;
        #pragma unroll
        for (int j = 0; j < 32; j++) { a1 += r1[j][threadIdx.x]; a2 += r2[j][threadIdx.x]; }
        float mu  = a1 * (1.f / (float)HCH);
        float var = a2 * (1.f / (float)HCH) - mu * mu;
        mu_s[threadIdx.x] = mu;
        rs_s[threadIdx.x] = rsqrtf(var + 1e-5f);
    }
    __syncthreads();
    float mu = mu_s[tx], rs = rs_s[tx];
    for (int h = hg; h < HCH; h += 32) {
        float g = gsm[h * 16 + tx];
        outp[h * LSEQ + l] = (g - mu) * rs * lng[h] + lnb[h];
    }
}

// ---------------- launch ----------------
extern "C" void kernel_launch(void* const* d_in, const int* in_sizes, int n_in,
                              void* d_out, int out_size) {
    const float* Z      = (const float*)d_in[0];
    const float* log_dt = (const float*)d_in[1];
    const float* Arl    = (const float*)d_in[2];
    const float* Aim    = (const float*)d_in[3];
    const float* Cre    = (const float*)d_in[4];
    const float* Cim    = (const float*)d_in[5];
    const float* Dsk    = (const float*)d_in[6];
    const float* gw     = (const float*)d_in[7];
    const float* gb     = (const float*)d_in[8];
    const float* lng    = (const float*)d_in[9];
    const float* lnb    = (const float*)d_in[10];
    float* out = (float*)d_out;

    kprep_kernel<<<(HCH * NM + 255) / 256, 256>>>(log_dt, Arl, Aim, Cre, Cim);
    asplit_kernel<<<(MPAD * KPAD) / 256, 256>>>(gw);

    const int srcs[4] = {-1, 0, 1, 0};
    const int dsts[4] = { 0, 1, 0, -1};
    for (int layer = 0; layer < 4; ++layer) {
        conv_kernel<<<HCH, 512>>>(Z, Dsk, srcs[layer]);
        gemm_hmma_kernel<<<dim3(16, 8, 3), 256>>>();
        lnglu_kernel<<<128, 512>>>(Z, gb, lng, lnb, out, srcs[layer], dsts[layer]);
    }
}